// round 10
// baseline (speedup 1.0000x reference)
#include <cuda_runtime.h>
#include <cuda_fp16.h>

#define NUM_USERS 30000
#define NN 60000            // total nodes
#define EE 800000           // edges
#define KK 64               // embed dim (4 intents x 16)
#define NB 235              // ceil(NN/256) scan blocks

// -------- device scratch --------
__device__ __half d_TT16[(size_t)NN * KK];   // fp16 tanh(per-intent l2norm(ego))
__device__ __half d_EGO16[(size_t)NN * KK];  // fp16 ego[n]/sqrt(deg[n])
__device__ float  d_SC[(size_t)EE * 4];      // softmax scores at SORTED edge pos
__device__ int    d_deg[NN];
__device__ float  d_ratio[NN * 4];           // sqrt(deg[n]) * rsqrt(deg2[n,intent])
__device__ int    d_rowptr[NN + 1];
__device__ int    d_cursor[NN];
__device__ int    d_sorted_t[EE];            // tails grouped by head
__device__ int    d_partial[256];            // scan block sums
__device__ unsigned d_bar = 0;               // monotonic grid-barrier counter

__device__ __forceinline__ const float4* ego_row(const float* Gu, const float* Gi, int t) {
    const float* p = (t < NUM_USERS) ? (Gu + (size_t)t * KK)
                                     : (Gi + (size_t)(t - NUM_USERS) * KK);
    return reinterpret_cast<const float4*>(p);
}

__device__ __forceinline__ float4 h4_to_f4(uint2 p) {
    float2 a = __half22float2(*reinterpret_cast<const __half2*>(&p.x));
    float2 b = __half22float2(*reinterpret_cast<const __half2*>(&p.y));
    return make_float4(a.x, a.y, b.x, b.y);
}

__device__ __forceinline__ float fast_tanh(float x) {   // |x|<=1 here
    float e = __expf(2.f * x);
    return __fdividef(e - 1.f, e + 1.f);
}

// single-wave monotonic grid barrier (replay-safe; all blocks co-resident)
__device__ __forceinline__ void gridbar() {
    __syncthreads();
    if (threadIdx.x == 0) {
        __threadfence();
        atomicAdd(&d_bar, 1u);
        unsigned token;
        asm volatile("ld.acquire.gpu.global.u32 %0, [%1];" : "=r"(token) : "l"(&d_bar) : "memory");
        unsigned target = ((token - 1u) / gridDim.x + 1u) * gridDim.x;
        unsigned v = token;
        while (v < target) {
            __nanosleep(32);
            asm volatile("ld.acquire.gpu.global.u32 %0, [%1];" : "=r"(v) : "l"(&d_bar) : "memory");
        }
    }
    __syncthreads();
}

// block-wide exclusive scan of one int per thread (blockDim=256)
__device__ __forceinline__ int block_exscan(int v, int* sm) {
    int lane = threadIdx.x & 31, w = threadIdx.x >> 5;
    int x = v;
#pragma unroll
    for (int d = 1; d < 32; d <<= 1) {
        int y = __shfl_up_sync(0xffffffffu, x, d);
        if (lane >= d) x += y;
    }
    if (lane == 31) sm[w] = x;
    __syncthreads();
    if (w == 0) {
        int s = (lane < 8) ? sm[lane] : 0;
#pragma unroll
        for (int d = 1; d < 8; d <<= 1) {
            int y = __shfl_up_sync(0xffffffffu, s, d);
            if (lane >= d) s += y;
        }
        if (lane < 8) sm[lane] = s;
    }
    __syncthreads();
    int off = (w > 0) ? sm[w - 1] : 0;
    return off + x - v;
}

// -------- kernels --------

#define DEG_BLKS  ((EE / 8 + 255) / 256)
#define SCAT_BLKS ((EE / 8 + 255) / 256)
#define NODE_BLKS ((NN * 16 + 255) / 256)

// fused: blocks [0, DEG_BLKS) count head degrees (8 edges/thread); rest TT16
__global__ void k_deg_tt(const int* __restrict__ eh,
                         const float* __restrict__ Gu, const float* __restrict__ Gi) {
    if (blockIdx.x < DEG_BLKS) {
        int g = blockIdx.x * blockDim.x + threadIdx.x;
        if (g >= EE / 8) return;
        int4 a = __ldg(&reinterpret_cast<const int4*>(eh)[2 * g]);
        int4 b = __ldg(&reinterpret_cast<const int4*>(eh)[2 * g + 1]);
        atomicAdd(&d_deg[a.x], 1); atomicAdd(&d_deg[a.y], 1);
        atomicAdd(&d_deg[a.z], 1); atomicAdd(&d_deg[a.w], 1);
        atomicAdd(&d_deg[b.x], 1); atomicAdd(&d_deg[b.y], 1);
        atomicAdd(&d_deg[b.z], 1); atomicAdd(&d_deg[b.w], 1);
    } else {
        int tid = (blockIdx.x - DEG_BLKS) * blockDim.x + threadIdx.x;
        if (tid >= NN * 16) return;
        int n = tid >> 4;
        float4 v = __ldg(&ego_row(Gu, Gi, n)[tid & 15]);
        float ss = v.x * v.x + v.y * v.y + v.z * v.z + v.w * v.w;
        ss += __shfl_xor_sync(0xffffffffu, ss, 1);
        ss += __shfl_xor_sync(0xffffffffu, ss, 2);
        float it = rsqrtf(fmaxf(ss, 1e-12f));
        __half2 t0 = __floats2half2_rn(fast_tanh(v.x * it), fast_tanh(v.y * it));
        __half2 t1 = __floats2half2_rn(fast_tanh(v.z * it), fast_tanh(v.w * it));
        uint2 tp; tp.x = *reinterpret_cast<unsigned*>(&t0);
                  tp.y = *reinterpret_cast<unsigned*>(&t1);
        reinterpret_cast<uint2*>(d_TT16)[tid] = tp;
    }
}

// fused two-stage scan in one kernel (NB blocks = single wave; gridbar safe)
__global__ void k_scan2() {
    __shared__ int sm[8];
    __shared__ int base_sh;
    int i = blockIdx.x * 256 + threadIdx.x;
    int v = (i < NN) ? d_deg[i] : 0;
    int ex = block_exscan(v, sm);
    if (threadIdx.x == 255) d_partial[blockIdx.x] = ex + v;
    gridbar();
    if (threadIdx.x < 32) {
        int s = 0;
        for (int t = threadIdx.x; t < blockIdx.x; t += 32) s += d_partial[t];
#pragma unroll
        for (int d = 16; d >= 1; d >>= 1) s += __shfl_xor_sync(0xffffffffu, s, d);
        if (threadIdx.x == 0) base_sh = s;
    }
    __syncthreads();
    ex += base_sh;
    if (i < NN) { d_rowptr[i] = ex; d_cursor[i] = ex; }
    if (i == NN - 1) d_rowptr[NN] = EE;
}

// fused: blocks [0, SCAT_BLKS) scatter tails (8 edges/thread); rest EGO16
__global__ void k_scatter_ego(const int* __restrict__ eh, const int* __restrict__ et,
                              const float* __restrict__ Gu, const float* __restrict__ Gi) {
    if (blockIdx.x < SCAT_BLKS) {
        int g = blockIdx.x * blockDim.x + threadIdx.x;
        if (g >= EE / 8) return;
        int4 ha = __ldg(&reinterpret_cast<const int4*>(eh)[2 * g]);
        int4 hb = __ldg(&reinterpret_cast<const int4*>(eh)[2 * g + 1]);
        int4 ta = __ldg(&reinterpret_cast<const int4*>(et)[2 * g]);
        int4 tb = __ldg(&reinterpret_cast<const int4*>(et)[2 * g + 1]);
        d_sorted_t[atomicAdd(&d_cursor[ha.x], 1)] = ta.x;
        d_sorted_t[atomicAdd(&d_cursor[ha.y], 1)] = ta.y;
        d_sorted_t[atomicAdd(&d_cursor[ha.z], 1)] = ta.z;
        d_sorted_t[atomicAdd(&d_cursor[ha.w], 1)] = ta.w;
        d_sorted_t[atomicAdd(&d_cursor[hb.x], 1)] = tb.x;
        d_sorted_t[atomicAdd(&d_cursor[hb.y], 1)] = tb.y;
        d_sorted_t[atomicAdd(&d_cursor[hb.z], 1)] = tb.z;
        d_sorted_t[atomicAdd(&d_cursor[hb.w], 1)] = tb.w;
    } else {
        int tid = (blockIdx.x - SCAT_BLKS) * blockDim.x + threadIdx.x;
        if (tid >= NN * 16) return;
        int n = tid >> 4;
        float4 v = __ldg(&ego_row(Gu, Gi, n)[tid & 15]);
        float w = rsqrtf((float)d_deg[n]);
        __half2 e0 = __floats2half2_rn(w * v.x, w * v.y);
        __half2 e1 = __floats2half2_rn(w * v.z, w * v.w);
        uint2 ep; ep.x = *reinterpret_cast<unsigned*>(&e0);
                  ep.y = *reinterpret_cast<unsigned*>(&e1);
        reinterpret_cast<uint2*>(d_EGO16)[tid] = ep;
    }
}

// Warp-per-row: SpMM1 (pipelined) -> l2norm -> transpose -> attention
// (slot,intent layout, pipelined) -> ratio.
__global__ void k_row1attn() {
    int wid = (blockIdx.x * blockDim.x + threadIdx.x) >> 5;
    if (wid >= NN) return;
    int lane = threadIdx.x & 31, half = lane >> 4, c = lane & 15;
    int start = d_rowptr[wid], end = d_rowptr[wid + 1];
    const uint2* EG = reinterpret_cast<const uint2*>(d_EGO16);

    // ---- pass 1: Z1 accumulate, software-pipelined (2 edges/iter per half) ----
    int jb = start + half;                      // this half's first edge position
    int n_my = (end - jb + 1) >> 1;             // #edges for this half
    if (end <= jb) n_my = 0;
    float4 acc = make_float4(0, 0, 0, 0);
    int t0 = (n_my > 0) ? __ldg(&d_sorted_t[jb]) : 0;
    int t1 = (n_my > 1) ? __ldg(&d_sorted_t[jb + 2]) : 0;
    for (int k = 0; k < n_my; k += 2) {
        float4 g0 = h4_to_f4(__ldg(&EG[(size_t)t0 * 16 + c]));
        float4 g1 = h4_to_f4(__ldg(&EG[(size_t)t1 * 16 + c]));   // junk ok if k+1>=n_my
        t0 = (k + 2 < n_my) ? __ldg(&d_sorted_t[jb + 2 * (k + 2)]) : 0;
        t1 = (k + 3 < n_my) ? __ldg(&d_sorted_t[jb + 2 * (k + 3)]) : 0;
        acc.x += g0.x; acc.y += g0.y; acc.z += g0.z; acc.w += g0.w;
        if (k + 1 < n_my) {
            acc.x += g1.x; acc.y += g1.y; acc.z += g1.z; acc.w += g1.w;
        }
    }
    acc.x += __shfl_xor_sync(0xffffffffu, acc.x, 16);
    acc.y += __shfl_xor_sync(0xffffffffu, acc.y, 16);
    acc.z += __shfl_xor_sync(0xffffffffu, acc.z, 16);
    acc.w += __shfl_xor_sync(0xffffffffu, acc.w, 16);
    float ss = acc.x * acc.x + acc.y * acc.y + acc.z * acc.z + acc.w * acc.w;
    ss += __shfl_xor_sync(0xffffffffu, ss, 1);
    ss += __shfl_xor_sync(0xffffffffu, ss, 2);
    float ih = rsqrtf(fmaxf(ss, 1e-12f));
    float4 hvf = make_float4(acc.x * ih, acc.y * ih, acc.z * ih, acc.w * ih);

    // ---- transpose hv into (slot,intent) layout: lane = 4*slot + intent ----
    int slot = lane >> 2, it = lane & 3;
    float hv[16];
#pragma unroll
    for (int k = 0; k < 16; k++) {
        int src = it * 4 + (k >> 2);
        float v;
        switch (k & 3) {
            case 0: v = __shfl_sync(0xffffffffu, hvf.x, src); break;
            case 1: v = __shfl_sync(0xffffffffu, hvf.y, src); break;
            case 2: v = __shfl_sync(0xffffffffu, hvf.z, src); break;
            default: v = __shfl_sync(0xffffffffu, hvf.w, src); break;
        }
        hv[k] = v;
    }

    // ---- pass 2: 8 edges/iter; lane=(slot,intent); pipelined idx loads ----
    float dsum = 0.f;
    int jp = start + slot;
    int tnext = (jp < end) ? __ldg(&d_sorted_t[jp]) : 0;
    for (int base = start; base < end; base += 8) {
        int tcur = tnext;
        bool act = (base + slot < end);
        int np = base + 8 + slot;
        tnext = (np < end) ? __ldg(&d_sorted_t[np]) : 0;
        const uint4* bp = reinterpret_cast<const uint4*>(d_TT16 + ((size_t)tcur << 6)) + (it << 1);
        uint4 q0 = __ldg(bp);
        uint4 q1 = __ldg(bp + 1);
        unsigned wreg[8] = {q0.x, q0.y, q0.z, q0.w, q1.x, q1.y, q1.z, q1.w};
        float p = 0.f;
#pragma unroll
        for (int k = 0; k < 8; k++) {
            float2 f = __half22float2(*reinterpret_cast<const __half2*>(&wreg[k]));
            p = fmaf(f.x, hv[2 * k], p);
            p = fmaf(f.y, hv[2 * k + 1], p);
        }
        float ex = __expf(p);                          // "1+" & max-shift cancel
        float sum = ex + __shfl_xor_sync(0xffffffffu, ex, 1);
        sum += __shfl_xor_sync(0xffffffffu, sum, 2);
        float sc = __fdividef(ex, sum);
        if (act) {
            d_SC[(size_t)(base + slot) * 4 + it] = sc; // coalesced
            dsum += sc;
        }
    }
    dsum += __shfl_xor_sync(0xffffffffu, dsum, 4);
    dsum += __shfl_xor_sync(0xffffffffu, dsum, 8);
    dsum += __shfl_xor_sync(0xffffffffu, dsum, 16);
    if (lane < 4)
        d_ratio[wid * 4 + it] = sqrtf((float)(end - start)) * rsqrtf(dsum);
}

// warp-per-row SpMM2 (fp16 ego, pipelined) + final mean -> out.
//   w = SC[j]*ratio[t]; EGO16[t]=ego[t]/sqrt(deg[t])  ==  SC[j]*rsqrt(deg2[t])*ego[t]
__global__ void k_row2(const float* __restrict__ Gu, const float* __restrict__ Gi,
                       float* __restrict__ out) {
    int wid = (blockIdx.x * blockDim.x + threadIdx.x) >> 5;
    if (wid >= NN) return;
    int lane = threadIdx.x & 31, half = lane >> 4, c = lane & 15;
    int intent = c >> 2;
    int start = d_rowptr[wid], end = d_rowptr[wid + 1];
    const uint2* EG = reinterpret_cast<const uint2*>(d_EGO16);

    int jb = start + half;
    int n_my = (end - jb + 1) >> 1;
    if (end <= jb) n_my = 0;
    float4 acc = make_float4(0, 0, 0, 0);
    int t0 = (n_my > 0) ? __ldg(&d_sorted_t[jb]) : 0;
    int t1 = (n_my > 1) ? __ldg(&d_sorted_t[jb + 2]) : 0;
    for (int k = 0; k < n_my; k += 2) {
        float w0 = __ldg(&d_SC[(size_t)(jb + 2 * k) * 4 + intent]) *
                   __ldg(&d_ratio[t0 * 4 + intent]);
        float w1 = (k + 1 < n_my)
                 ? __ldg(&d_SC[(size_t)(jb + 2 * (k + 1)) * 4 + intent]) *
                   __ldg(&d_ratio[t1 * 4 + intent])
                 : 0.f;
        float4 g0 = h4_to_f4(__ldg(&EG[(size_t)t0 * 16 + c]));
        float4 g1 = h4_to_f4(__ldg(&EG[(size_t)t1 * 16 + c]));
        t0 = (k + 2 < n_my) ? __ldg(&d_sorted_t[jb + 2 * (k + 2)]) : 0;
        t1 = (k + 3 < n_my) ? __ldg(&d_sorted_t[jb + 2 * (k + 3)]) : 0;
        acc.x += w0 * g0.x + w1 * g1.x;
        acc.y += w0 * g0.y + w1 * g1.y;
        acc.z += w0 * g0.z + w1 * g1.z;
        acc.w += w0 * g0.w + w1 * g1.w;
    }
    acc.x += __shfl_xor_sync(0xffffffffu, acc.x, 16);
    acc.y += __shfl_xor_sync(0xffffffffu, acc.y, 16);
    acc.z += __shfl_xor_sync(0xffffffffu, acc.z, 16);
    acc.w += __shfl_xor_sync(0xffffffffu, acc.w, 16);
    if (half == 0) {
        float r2 = d_ratio[wid * 4 + intent] * rsqrtf((float)(end - start));
        float4 a = __ldg(&ego_row(Gu, Gi, wid)[c]);   // self term fp32
        reinterpret_cast<float4*>(out)[(size_t)wid * 16 + c] =
            make_float4(0.5f * (a.x + r2 * acc.x), 0.5f * (a.y + r2 * acc.y),
                        0.5f * (a.z + r2 * acc.z), 0.5f * (a.w + r2 * acc.w));
    }
}

extern "C" void kernel_launch(void* const* d_in, const int* in_sizes, int n_in,
                              void* d_out, int out_size) {
    const float* Gu = (const float*)d_in[0];
    const float* Gi = (const float*)d_in[1];
    const int*   eh = (const int*)d_in[2];
    const int*   et = (const int*)d_in[3];
    float* out = (float*)d_out;

    void* degp = nullptr;
    cudaGetSymbolAddress(&degp, d_deg);
    cudaMemsetAsync(degp, 0, NN * sizeof(int));

    const int T = 256;
    const int ROWG = (NN * 32 + T - 1) / T;   // warp-per-row grids
    k_deg_tt     <<<DEG_BLKS + NODE_BLKS, T>>>(eh, Gu, Gi);
    k_scan2      <<<NB, 256>>>();
    k_scatter_ego<<<SCAT_BLKS + NODE_BLKS, T>>>(eh, et, Gu, Gi);
    k_row1attn   <<<ROWG, T>>>();
    k_row2       <<<ROWG, T>>>(Gu, Gi, out);
}